// round 13
// baseline (speedup 1.0000x reference)
#include <cuda_runtime.h>
#include <cuda_fp16.h>
#include <math.h>

// Problem constants
#define BB   4
#define SS   2048
#define DD   1024
#define HH   16
#define DKK  64
#define DFFq 4096
#define ROWS (BB*SS)          // 8192

// ---------------------------------------------------------------------------
// Scratch (device globals; no allocation allowed)
// ---------------------------------------------------------------------------
__device__ float g_q  [ (size_t)ROWS*DD ];
__device__ float g_k  [ (size_t)ROWS*DD ];
__device__ float g_v  [ (size_t)ROWS*DD ];
__device__ float g_ctx[ (size_t)ROWS*DD ];
__device__ float g_t0 [ (size_t)ROWS*DD ];
__device__ float g_x1 [ (size_t)ROWS*DD ];
__device__ float g_hb [ (size_t)ROWS*DFFq ];

// ---------------------------------------------------------------------------
// fp16 helpers
// ---------------------------------------------------------------------------
__device__ __forceinline__ unsigned pack_h2(float a, float b) {
    __half2 h = __floats2half2_rn(a, b);
    return *(unsigned*)&h;
}

__device__ __forceinline__ void mma_f16(float* c, const unsigned* a, const unsigned* b) {
    asm volatile(
        "mma.sync.aligned.m16n8k16.row.col.f32.f16.f16.f32 "
        "{%0,%1,%2,%3}, {%4,%5,%6,%7}, {%8,%9}, {%0,%1,%2,%3};"
        : "+f"(c[0]), "+f"(c[1]), "+f"(c[2]), "+f"(c[3])
        : "r"(a[0]), "r"(a[1]), "r"(a[2]), "r"(a[3]),
          "r"(b[0]), "r"(b[1]));
}

// ---------------------------------------------------------------------------
// GEMM (tensor-core fp16, fp32 accumulate):
// C[M,N] = A[M,K] * Bw[N,K]^T + bias (+Res)(+relu)
// CTA tile 128x128, BK=32, 8 warps, warp tile 64x32 (4x4 m16n8k16 tiles,
// 2 k-steps). Smem rows = 40 halves (word stride 20: bank 20g+q all
// distinct -> conflict-free fragment LDS).
// ---------------------------------------------------------------------------
#define HPAD 40

template<int RELU, int RES>
__global__ void __launch_bounds__(256, 2)
gemm_f16(const float* __restrict__ A, const float* __restrict__ Bw,
         const float* __restrict__ bias, const float* __restrict__ Res,
         float* __restrict__ C, int M, int N, int K)
{
    __shared__ __align__(16) __half As[128 * HPAD];
    __shared__ __align__(16) __half Bs[128 * HPAD];

    const int t = threadIdx.x;
    const int w = t >> 5, lane = t & 31;
    const int gid = lane >> 2, qid = lane & 3;
    const int bm = blockIdx.y, bn = blockIdx.x;
    const int wm = (w >> 2) * 64;
    const int wn = (w & 3) * 32;

    const int r0 = t >> 3;          // 0..31
    const int qc = t & 7;           // 0..7

    const float* Ap = A  + (size_t)(bm*128 + r0) * K + qc*4;
    const float* Bp = Bw + (size_t)(bn*128 + r0) * K + qc*4;

    float pa[16], pb[16];
#pragma unroll
    for (int i = 0; i < 4; i++) {
        float4 va = *(const float4*)(Ap + (size_t)(32*i) * K);
        float4 vb = *(const float4*)(Bp + (size_t)(32*i) * K);
        pa[i*4+0]=va.x; pa[i*4+1]=va.y; pa[i*4+2]=va.z; pa[i*4+3]=va.w;
        pb[i*4+0]=vb.x; pb[i*4+1]=vb.y; pb[i*4+2]=vb.z; pb[i*4+3]=vb.w;
    }

    float acc[4][4][4];
#pragma unroll
    for (int i = 0; i < 4; i++)
#pragma unroll
        for (int j = 0; j < 4; j++)
#pragma unroll
            for (int c = 0; c < 4; c++) acc[i][j][c] = 0.f;

    for (int k0 = 0; k0 < K; k0 += 32) {
        __syncthreads();
#pragma unroll
        for (int i = 0; i < 4; i++) {
            uint2 sa, sb;
            sa.x = pack_h2(pa[i*4+0], pa[i*4+1]);
            sa.y = pack_h2(pa[i*4+2], pa[i*4+3]);
            sb.x = pack_h2(pb[i*4+0], pb[i*4+1]);
            sb.y = pack_h2(pb[i*4+2], pb[i*4+3]);
            *(uint2*)&As[(r0 + 32*i) * HPAD + qc*4] = sa;
            *(uint2*)&Bs[(r0 + 32*i) * HPAD + qc*4] = sb;
        }
        __syncthreads();

        if (k0 + 32 < K) {
#pragma unroll
            for (int i = 0; i < 4; i++) {
                float4 va = *(const float4*)(Ap + (size_t)(32*i) * K + (k0 + 32));
                float4 vb = *(const float4*)(Bp + (size_t)(32*i) * K + (k0 + 32));
                pa[i*4+0]=va.x; pa[i*4+1]=va.y; pa[i*4+2]=va.z; pa[i*4+3]=va.w;
                pb[i*4+0]=vb.x; pb[i*4+1]=vb.y; pb[i*4+2]=vb.z; pb[i*4+3]=vb.w;
            }
        }

#pragma unroll
        for (int ks = 0; ks < 2; ks++) {
            const int kk = ks * 16;
            unsigned afr[4][4], bfr[4][2];
#pragma unroll
            for (int i = 0; i < 4; i++) {
                const int r = wm + i*16 + gid;
                afr[i][0] = *(const unsigned*)&As[r      *HPAD + kk + 2*qid];
                afr[i][1] = *(const unsigned*)&As[(r + 8)*HPAD + kk + 2*qid];
                afr[i][2] = *(const unsigned*)&As[r      *HPAD + kk + 2*qid + 8];
                afr[i][3] = *(const unsigned*)&As[(r + 8)*HPAD + kk + 2*qid + 8];
            }
#pragma unroll
            for (int j = 0; j < 4; j++) {
                const int n = wn + j*8 + gid;
                bfr[j][0] = *(const unsigned*)&Bs[n*HPAD + kk + 2*qid];
                bfr[j][1] = *(const unsigned*)&Bs[n*HPAD + kk + 2*qid + 8];
            }
#pragma unroll
            for (int i = 0; i < 4; i++)
#pragma unroll
                for (int j = 0; j < 4; j++)
                    mma_f16(acc[i][j], afr[i], bfr[j]);
        }
    }

#pragma unroll
    for (int i = 0; i < 4; i++) {
#pragma unroll
        for (int j = 0; j < 4; j++) {
            const int row = bm*128 + wm + i*16 + gid;
            const int col = bn*128 + wn + j*8 + 2*qid;
            float2 bi = *(const float2*)&bias[col];
            float2 r0v, r1v;
            r0v.x = acc[i][j][0] + bi.x;  r0v.y = acc[i][j][1] + bi.y;
            r1v.x = acc[i][j][2] + bi.x;  r1v.y = acc[i][j][3] + bi.y;
            if (RES) {
                float2 a0 = *(const float2*)&Res[(size_t)row*N + col];
                float2 a1 = *(const float2*)&Res[(size_t)(row+8)*N + col];
                r0v.x += a0.x; r0v.y += a0.y;
                r1v.x += a1.x; r1v.y += a1.y;
            }
            if (RELU) {
                r0v.x = fmaxf(r0v.x, 0.f); r0v.y = fmaxf(r0v.y, 0.f);
                r1v.x = fmaxf(r1v.x, 0.f); r1v.y = fmaxf(r1v.y, 0.f);
            }
            *(float2*)&C[(size_t)row    *N + col] = r0v;
            *(float2*)&C[(size_t)(row+8)*N + col] = r1v;
        }
    }
}

// ---------------------------------------------------------------------------
// Flash attention (tensor core fp16, fp32 accum/softmax):
// CTA = 128 queries x one head, 8 warps x 16 rows, 64-key tiles, m16n8k16.
// Rows padded to 72 halves (word stride 36: bank 4g+q distinct ->
// conflict-free). Smem 55.5KB -> 2 CTAs/SM.
// ---------------------------------------------------------------------------
#define AP2 72

__global__ void __launch_bounds__(256, 2)
attn_tc(const float* __restrict__ Q, const float* __restrict__ Kf,
        const float* __restrict__ Vf, const int* __restrict__ mask,
        float* __restrict__ ctx)
{
    extern __shared__ __half smh[];
    __half* Qs = smh;                      // [128][AP2]
    __half* Ks = Qs + 128*AP2;             // [64][AP2]   K[c][d]
    __half* Vt = Ks + 64*AP2;              // [64][AP2]   V^T[d][c]
    __half* Ps = Vt + 64*AP2;              // [128][AP2]
    int*   msk = (int*)(Ps + 128*AP2);     // [64]

    const int t = threadIdx.x, w = t >> 5, lane = t & 31;
    const int gid = lane >> 2, qid = lane & 3;
    const int qb = blockIdx.x, bh = blockIdx.y;
    const int b = bh / HH, h = bh % HH;
    const int wm = w * 16;

    const size_t base = (size_t)b * SS * DD + (size_t)h * DKK;

    // --- load Q tile (128x64), prescale 1/8, pack fp16 ---
    {
        const int r = t >> 1, c0 = (t & 1) * 32;
        const float* qp = Q + base + (size_t)(qb*128 + r) * DD + c0;
#pragma unroll
        for (int i = 0; i < 32; i += 8) {
            float4 v0 = *(const float4*)(qp + i);
            float4 v1 = *(const float4*)(qp + i + 4);
            uint4 s;
            s.x = pack_h2(v0.x*0.125f, v0.y*0.125f);
            s.y = pack_h2(v0.z*0.125f, v0.w*0.125f);
            s.z = pack_h2(v1.x*0.125f, v1.y*0.125f);
            s.w = pack_h2(v1.z*0.125f, v1.w*0.125f);
            *(uint4*)&Qs[r*AP2 + c0 + i] = s;
        }
    }

    float m0 = -1e30f, m1 = -1e30f, l0 = 0.f, l1 = 0.f;
    float o[8][4];
#pragma unroll
    for (int j = 0; j < 8; j++)
#pragma unroll
        for (int c = 0; c < 4; c++) o[j][c] = 0.f;

    for (int kc = 0; kc < SS; kc += 64) {
        __syncthreads();
        {
            const int r = t >> 2, c0 = (t & 3) * 16;
            const float* kp = Kf + base + (size_t)(kc + r) * DD + c0;
            const float* vp = Vf + base + (size_t)(kc + r) * DD + c0;
#pragma unroll
            for (int i = 0; i < 16; i += 8) {
                float4 k0v = *(const float4*)(kp + i);
                float4 k1v = *(const float4*)(kp + i + 4);
                uint4 s;
                s.x = pack_h2(k0v.x, k0v.y); s.y = pack_h2(k0v.z, k0v.w);
                s.z = pack_h2(k1v.x, k1v.y); s.w = pack_h2(k1v.z, k1v.w);
                *(uint4*)&Ks[r*AP2 + c0 + i] = s;
                float4 v0v = *(const float4*)(vp + i);
                float4 v1v = *(const float4*)(vp + i + 4);
                Vt[(c0+i+0)*AP2 + r] = __float2half_rn(v0v.x);
                Vt[(c0+i+1)*AP2 + r] = __float2half_rn(v0v.y);
                Vt[(c0+i+2)*AP2 + r] = __float2half_rn(v0v.z);
                Vt[(c0+i+3)*AP2 + r] = __float2half_rn(v0v.w);
                Vt[(c0+i+4)*AP2 + r] = __float2half_rn(v1v.x);
                Vt[(c0+i+5)*AP2 + r] = __float2half_rn(v1v.y);
                Vt[(c0+i+6)*AP2 + r] = __float2half_rn(v1v.z);
                Vt[(c0+i+7)*AP2 + r] = __float2half_rn(v1v.w);
            }
            if (t < 64) msk[t] = mask[(size_t)b * SS + kc + t];
        }
        __syncthreads();

        // --- S = Q K^T ---
        float sacc[8][4];
#pragma unroll
        for (int j = 0; j < 8; j++)
#pragma unroll
            for (int c = 0; c < 4; c++) sacc[j][c] = 0.f;

#pragma unroll
        for (int kk = 0; kk < 64; kk += 16) {
            unsigned a[4];
            a[0] = *(const unsigned*)&Qs[(wm+gid)  *AP2 + kk + 2*qid];
            a[1] = *(const unsigned*)&Qs[(wm+gid+8)*AP2 + kk + 2*qid];
            a[2] = *(const unsigned*)&Qs[(wm+gid)  *AP2 + kk + 2*qid + 8];
            a[3] = *(const unsigned*)&Qs[(wm+gid+8)*AP2 + kk + 2*qid + 8];
#pragma unroll
            for (int j = 0; j < 8; j++) {
                unsigned bf[2];
                bf[0] = *(const unsigned*)&Ks[(8*j+gid)*AP2 + kk + 2*qid];
                bf[1] = *(const unsigned*)&Ks[(8*j+gid)*AP2 + kk + 2*qid + 8];
                mma_f16(sacc[j], a, bf);
            }
        }

        // --- mask ---
#pragma unroll
        for (int j = 0; j < 8; j++) {
            const int c = 8*j + 2*qid;
            if (msk[c]   == 0) { sacc[j][0] = -1e9f; sacc[j][2] = -1e9f; }
            if (msk[c+1] == 0) { sacc[j][1] = -1e9f; sacc[j][3] = -1e9f; }
        }

        // --- online softmax (rows gid, gid+8) ---
        float mt0 = -1e30f, mt1 = -1e30f;
#pragma unroll
        for (int j = 0; j < 8; j++) {
            mt0 = fmaxf(mt0, fmaxf(sacc[j][0], sacc[j][1]));
            mt1 = fmaxf(mt1, fmaxf(sacc[j][2], sacc[j][3]));
        }
        mt0 = fmaxf(mt0, __shfl_xor_sync(0xffffffffu, mt0, 1));
        mt0 = fmaxf(mt0, __shfl_xor_sync(0xffffffffu, mt0, 2));
        mt1 = fmaxf(mt1, __shfl_xor_sync(0xffffffffu, mt1, 1));
        mt1 = fmaxf(mt1, __shfl_xor_sync(0xffffffffu, mt1, 2));

        const float mn0 = fmaxf(m0, mt0), mn1 = fmaxf(m1, mt1);
        const float al0 = __expf(m0 - mn0), al1 = __expf(m1 - mn1);
        m0 = mn0; m1 = mn1;

        float ps0 = 0.f, ps1 = 0.f;
#pragma unroll
        for (int j = 0; j < 8; j++) {
            float p00 = __expf(sacc[j][0] - mn0);
            float p01 = __expf(sacc[j][1] - mn0);
            float p10 = __expf(sacc[j][2] - mn1);
            float p11 = __expf(sacc[j][3] - mn1);
            ps0 += p00 + p01;  ps1 += p10 + p11;
            *(unsigned*)&Ps[(wm+gid)  *AP2 + 8*j + 2*qid] = pack_h2(p00, p01);
            *(unsigned*)&Ps[(wm+gid+8)*AP2 + 8*j + 2*qid] = pack_h2(p10, p11);
        }
        ps0 += __shfl_xor_sync(0xffffffffu, ps0, 1);
        ps0 += __shfl_xor_sync(0xffffffffu, ps0, 2);
        ps1 += __shfl_xor_sync(0xffffffffu, ps1, 1);
        ps1 += __shfl_xor_sync(0xffffffffu, ps1, 2);
        l0 = l0 * al0 + ps0;
        l1 = l1 * al1 + ps1;

#pragma unroll
        for (int j = 0; j < 8; j++) {
            o[j][0] *= al0; o[j][1] *= al0;
            o[j][2] *= al1; o[j][3] *= al1;
        }
        __syncwarp();   // Ps rows are warp-local

        // --- O += P V ---
#pragma unroll
        for (int kk = 0; kk < 64; kk += 16) {
            unsigned a[4];
            a[0] = *(const unsigned*)&Ps[(wm+gid)  *AP2 + kk + 2*qid];
            a[1] = *(const unsigned*)&Ps[(wm+gid+8)*AP2 + kk + 2*qid];
            a[2] = *(const unsigned*)&Ps[(wm+gid)  *AP2 + kk + 2*qid + 8];
            a[3] = *(const unsigned*)&Ps[(wm+gid+8)*AP2 + kk + 2*qid + 8];
#pragma unroll
            for (int j = 0; j < 8; j++) {
                unsigned bf[2];
                bf[0] = *(const unsigned*)&Vt[(8*j+gid)*AP2 + kk + 2*qid];
                bf[1] = *(const unsigned*)&Vt[(8*j+gid)*AP2 + kk + 2*qid + 8];
                mma_f16(o[j], a, bf);
            }
        }
    }

    // --- epilogue ---
    const float inv0 = 1.0f / l0, inv1 = 1.0f / l1;
    const int row = qb*128 + wm + gid;
#pragma unroll
    for (int j = 0; j < 8; j++) {
        const int col = 8*j + 2*qid;
        float2 r0v, r1v;
        r0v.x = o[j][0]*inv0; r0v.y = o[j][1]*inv0;
        r1v.x = o[j][2]*inv1; r1v.y = o[j][3]*inv1;
        *(float2*)&ctx[base + (size_t)row    *DD + col] = r0v;
        *(float2*)&ctx[base + (size_t)(row+8)*DD + col] = r1v;
    }
}

// ---------------------------------------------------------------------------
// LayerNorm: unbiased std (ddof=1), eps added to std
// ---------------------------------------------------------------------------
__global__ void __launch_bounds__(256)
ln_kernel(const float* __restrict__ in, const float* __restrict__ g,
          const float* __restrict__ be, float* __restrict__ out)
{
    __shared__ float red1[8];
    __shared__ float red2[8];
    const int row = blockIdx.x;
    const int t = threadIdx.x;
    const int warp = t >> 5, lane = t & 31;

    float4 v = *(const float4*)(in + (size_t)row * DD + t*4);

    float s = v.x + v.y + v.z + v.w;
#pragma unroll
    for (int off = 16; off; off >>= 1) s += __shfl_xor_sync(0xffffffffu, s, off);
    if (lane == 0) red1[warp] = s;
    __syncthreads();
    float tot = 0.f;
#pragma unroll
    for (int i = 0; i < 8; i++) tot += red1[i];
    const float mean = tot * (1.0f / DD);

    float dx = v.x - mean, dy = v.y - mean, dz = v.z - mean, dw = v.w - mean;
    float sq = dx*dx + dy*dy + dz*dz + dw*dw;
#pragma unroll
    for (int off = 16; off; off >>= 1) sq += __shfl_xor_sync(0xffffffffu, sq, off);
    if (lane == 0) red2[warp] = sq;
    __syncthreads();
    float sqtot = 0.f;
#pragma unroll
    for (int i = 0; i < 8; i++) sqtot += red2[i];

    const float var = sqtot * (1.0f / (DD - 1));
    const float inv = 1.0f / (sqrtf(var) + 1e-6f);

    float4 gv = *(const float4*)(g  + t*4);
    float4 bv = *(const float4*)(be + t*4);
    float4 r;
    r.x = dx * inv * gv.x + bv.x;
    r.y = dy * inv * gv.y + bv.y;
    r.z = dz * inv * gv.z + bv.z;
    r.w = dw * inv * gv.w + bv.w;
    *(float4*)(out + (size_t)row * DD + t*4) = r;
}

// ---------------------------------------------------------------------------
// kernel_launch
// ---------------------------------------------------------------------------
extern "C" void kernel_launch(void* const* d_in, const int* in_sizes, int n_in,
                              void* d_out, int out_size)
{
    const float* x    = (const float*)d_in[0];
    const int*   mask = (const int*)  d_in[1];
    const float* Wq = (const float*)d_in[2];  const float* bq = (const float*)d_in[3];
    const float* Wk = (const float*)d_in[4];  const float* bk = (const float*)d_in[5];
    const float* Wv = (const float*)d_in[6];  const float* bv = (const float*)d_in[7];
    const float* Wo = (const float*)d_in[8];  const float* bo = (const float*)d_in[9];
    const float* W1 = (const float*)d_in[10]; const float* b1 = (const float*)d_in[11];
    const float* W2 = (const float*)d_in[12]; const float* b2 = (const float*)d_in[13];
    const float* g1 = (const float*)d_in[14]; const float* be1 = (const float*)d_in[15];
    const float* g2 = (const float*)d_in[16]; const float* be2 = (const float*)d_in[17];
    float* out = (float*)d_out;

    float *pq, *pk, *pv, *pctx, *pt0, *px1, *ph;
    cudaGetSymbolAddress((void**)&pq,   g_q);
    cudaGetSymbolAddress((void**)&pk,   g_k);
    cudaGetSymbolAddress((void**)&pv,   g_v);
    cudaGetSymbolAddress((void**)&pctx, g_ctx);
    cudaGetSymbolAddress((void**)&pt0,  g_t0);
    cudaGetSymbolAddress((void**)&px1,  g_x1);
    cudaGetSymbolAddress((void**)&ph,   g_hb);

    const int attn_smem = (128*AP2 + 64*AP2 + 64*AP2 + 128*AP2) * 2 + 64*4;
    cudaFuncSetAttribute(attn_tc, cudaFuncAttributeMaxDynamicSharedMemorySize,
                         attn_smem);

    dim3 blk(256);
    dim3 gD(DD/128,   ROWS/128);
    dim3 gF(DFFq/128, ROWS/128);

    // QKV projections (fp16 tensor core)
    gemm_f16<0,0><<<gD, blk>>>(x, Wq, bq, nullptr, pq, ROWS, DD, DD);
    gemm_f16<0,0><<<gD, blk>>>(x, Wk, bk, nullptr, pk, ROWS, DD, DD);
    gemm_f16<0,0><<<gD, blk>>>(x, Wv, bv, nullptr, pv, ROWS, DD, DD);

    // attention (fp16 tensor core)
    attn_tc<<<dim3(SS/128, BB*HH), blk, attn_smem>>>(pq, pk, pv, mask, pctx);

    // output projection + residual, then LN1
    gemm_f16<0,1><<<gD, blk>>>(pctx, Wo, bo, x, pt0, ROWS, DD, DD);
    ln_kernel<<<ROWS, blk>>>(pt0, g1, be1, px1);

    // FFN
    gemm_f16<1,0><<<gF, blk>>>(px1, W1, b1, nullptr, ph, ROWS, DFFq, DD);
    gemm_f16<0,1><<<gD, blk>>>(ph, W2, b2, px1, pt0, ROWS, DD, DFFq);

    // LN2 -> output
    ln_kernel<<<ROWS, blk>>>(pt0, g2, be2, out);
}